// round 8
// baseline (speedup 1.0000x reference)
#include <cuda_runtime.h>
#include <cuda_bf16.h>
#include <cstdint>

#define MAXL 16
#define S    8           // slices per request: 32000 float4 / 8 = 4000
#define TPB  256
#define MAXB 1024

// Zero-initialized scratch; g_count self-resets -> graph-replay safe.
__device__ unsigned long long g_slot[MAXB * S];
__device__ int                g_count[MAXB];

__global__ void __launch_bounds__(TPB)
fused_rejection_kernel(
    const float* __restrict__ draft_probs,
    const float* __restrict__ target_probs,
    const float* __restrict__ uniform_probs,
    const int*   __restrict__ draft_token_ids,
    const int*   __restrict__ cu,
    const int*   __restrict__ bonus,
    float*       __restrict__ out,
    int V, int NT, int L)
{
    const int s   = blockIdx.x;   // slice
    const int b   = blockIdx.y;   // request
    const int tid = threadIdx.x;

    __shared__ int      s_dids[MAXL];
    __shared__ float    s_tp[MAXL], s_dp[MAXL], s_u[MAXL];
    __shared__ int      s_last, s_rejected, s_write_col, s_recrow;
    __shared__ float    s_wmax[TPB / 32];
    __shared__ float    s_bmax;
    __shared__ unsigned s_minidx;

    const int prev   = (b == 0) ? 0 : __ldg(&cu[b - 1]);
    const int ndraft = __ldg(&cu[b]) - prev;
    const int n      = ndraft < L ? ndraft : L;

    // Per-block gather (L2-hot across blocks/replays) + acceptance scan.
    if (tid < n && n > 0) {
        long long gidx = (long long)(prev + tid);
        int d = __ldg(&draft_token_ids[gidx]);
        s_dids[tid] = d;
        s_tp[tid] = __ldg(&target_probs[gidx * (long long)V + d]);
        s_dp[tid] = __ldg(&draft_probs [gidx * (long long)V + d]);
        s_u [tid] = __ldg(&uniform_probs[gidx]);
    }
    if (tid == 0) s_minidx = 0xFFFFFFFFu;
    __syncthreads();

    if (tid == 0) {
        float pi = 1.0f, U = 1.0f;
        int last = -1;
        for (int i = 0; i < n; i++) {
            float dp = s_dp[i];
            float r  = (dp > 0.0f) ? (s_tp[i] / dp) : 1.0f;
            pi = fminf(pi * r, 1.0f);
            U  = U * s_u[i];
            if ((dp > 0.0f) && (pi >= U)) last = i;
        }
        int rejected = (ndraft > 0) && (last != ndraft - 1);
        int rr = prev + last + 1;
        s_recrow    = max(0, min(rr, NT - 1));
        s_last      = last;
        s_rejected  = rejected;
        s_write_col = rejected ? (last + 1) : n;
    }
    __syncthreads();

    if (s == 0 && tid <= L) {
        int val = (tid < L && tid <= s_last) ? s_dids[tid] : -1;
        if (tid == s_write_col)
            val = s_rejected ? -1 : __ldg(&bonus[b]);
        out[b * (L + 1) + tid] = (float)val;
    }

    if (!s_rejected) return;

    const int nv4_tot = V >> 2;
    const int chunk4  = (nv4_tot + S - 1) / S;         // 4000 for V=128000
    const int start4  = s * chunk4;
    const int end4    = min(nv4_tot, start4 + chunk4);
    const int n4      = end4 - start4;
    const float4* __restrict__ row4 =
        (const float4*)target_probs + (long long)s_recrow * nv4_tot + start4;
    const float* __restrict__ row = target_probs + (long long)s_recrow * V;

    // ---- Pass A: pure value max (no index tracking -> free MLP) ----
    float m0 = -1.0f, m1 = -1.0f, m2 = -1.0f, m3 = -1.0f;
    #pragma unroll 8
    for (int j = tid; j < n4; j += TPB) {
        float4 v = row4[j];
        m0 = fmaxf(m0, v.x);
        m1 = fmaxf(m1, v.y);
        m2 = fmaxf(m2, v.z);
        m3 = fmaxf(m3, v.w);
    }
    float m = fmaxf(fmaxf(m0, m1), fmaxf(m2, m3));
    if (s == S - 1) {                     // scalar tail (V % 4 != 0 only)
        for (int i = (nv4_tot << 2) + tid; i < V; i += TPB)
            m = fmaxf(m, row[i]);
    }
    #pragma unroll
    for (int off = 16; off > 0; off >>= 1)
        m = fmaxf(m, __shfl_down_sync(0xFFFFFFFFu, m, off));
    if ((tid & 31) == 0) s_wmax[tid >> 5] = m;
    __syncthreads();
    if (tid < 32) {
        float v = (tid < (TPB / 32)) ? s_wmax[tid] : -1.0f;
        #pragma unroll
        for (int off = 16; off > 0; off >>= 1)
            v = fmaxf(v, __shfl_down_sync(0xFFFFFFFFu, v, off));
        if (tid == 0) s_bmax = v;
    }
    __syncthreads();

    // ---- Pass B: first index equal to block max (re-read is L2-hot) ----
    const unsigned mb = __float_as_uint(s_bmax);   // probs >= 0: bit equality ok
    unsigned lmin = 0xFFFFFFFFu;
    #pragma unroll 8
    for (int j = tid; j < n4; j += TPB) {
        float4 v = row4[j];
        unsigned gi = (unsigned)((start4 + j) << 2);
        if (__float_as_uint(v.x) == mb) lmin = min(lmin, gi);
        if (__float_as_uint(v.y) == mb) lmin = min(lmin, gi + 1);
        if (__float_as_uint(v.z) == mb) lmin = min(lmin, gi + 2);
        if (__float_as_uint(v.w) == mb) lmin = min(lmin, gi + 3);
    }
    if (s == S - 1) {
        for (int i = (nv4_tot << 2) + tid; i < V; i += TPB)
            if (__float_as_uint(row[i]) == mb) lmin = min(lmin, (unsigned)i);
    }
    if (lmin != 0xFFFFFFFFu) atomicMin(&s_minidx, lmin);
    __syncthreads();

    // ---- publish slot; last block finalizes ----
    if (tid == 0) {
        unsigned long long key =
            ((unsigned long long)mb << 32) | (0xFFFFFFFFu - s_minidx);
        g_slot[b * S + s] = key;
        __threadfence();
        int old = atomicAdd(&g_count[b], 1);
        if (old == S - 1) {
            unsigned long long best = 0ull;
            #pragma unroll
            for (int j = 0; j < S; j++) {
                unsigned long long w = g_slot[b * S + j];
                if (w > best) best = w;
            }
            int rec = (int)(0xFFFFFFFFu - (unsigned)(best & 0xFFFFFFFFull));
            out[b * (L + 1) + s_write_col] = (float)rec;
            g_count[b] = 0;    // self-reset for next replay
        }
    }
}

extern "C" void kernel_launch(void* const* d_in, const int* in_sizes, int n_in,
                              void* d_out, int out_size) {
    const float* draft_probs     = (const float*)d_in[0];
    const float* target_probs    = (const float*)d_in[1];
    const float* uniform_probs   = (const float*)d_in[2];
    const int*   draft_token_ids = (const int*)  d_in[3];
    const int*   cu              = (const int*)  d_in[4];
    const int*   bonus           = (const int*)  d_in[5];
    float*       out             = (float*)d_out;

    const int NT = in_sizes[2];
    const int V  = in_sizes[0] / NT;
    const int B  = in_sizes[4];
    const int L  = out_size / B - 1;

    fused_rejection_kernel<<<dim3(S, B), TPB>>>(
        draft_probs, target_probs, uniform_probs,
        draft_token_ids, cu, bonus, out, V, NT, L);
}

// round 10
// speedup vs baseline: 1.4800x; 1.4800x over previous
#include <cuda_runtime.h>
#include <cuda_bf16.h>
#include <cstdint>

#define MAXL   16
#define S      16         // slices per request
#define TPB    256
#define MAXB   1024
#define MAXNT  2048
#define BUF_F4 2048       // smem staging capacity (float4) = 32 KB

// Zero-initialized scratch; g_count self-resets -> graph-replay safe.
__device__ unsigned long long g_slot[MAXB * S];
__device__ int                g_count[MAXB];
__device__ int4               g_meta[MAXB];   // x=rejected, y=rec_row, z=write_col

// ---------------------------------------------------------------------------
// Kernel A: ONE block. All token gathers issued in parallel (2 dependent load
// rounds total), then a thread-per-request scan. Writes meta + base out rows.
// ---------------------------------------------------------------------------
__global__ void __launch_bounds__(512)
scan_kernel(const float* __restrict__ draft_probs,
            const float* __restrict__ target_probs,
            const float* __restrict__ uniform_probs,
            const int*   __restrict__ ids,
            const int*   __restrict__ cu,
            const int*   __restrict__ bonus,
            float*       __restrict__ out,
            int V, int NT, int B, int L)
{
    __shared__ float s_r[MAXNT], s_u[MAXNT];
    __shared__ unsigned char s_ok[MAXNT];
    __shared__ int   s_d[MAXNT];
    __shared__ int   s_cu[MAXB];
    const int tid = threadIdx.x;

    for (int t = tid; t < B; t += blockDim.x) s_cu[t] = __ldg(&cu[t]);
    for (int t = tid; t < NT && t < MAXNT; t += blockDim.x) {
        int d = __ldg(&ids[t]);
        float tp = __ldg(&target_probs[(long long)t * V + d]);
        float dv = __ldg(&draft_probs [(long long)t * V + d]);
        s_d[t]  = d;
        s_r[t]  = (dv > 0.0f) ? (tp / dv) : 1.0f;
        s_u[t]  = __ldg(&uniform_probs[t]);
        s_ok[t] = (dv > 0.0f) ? 1 : 0;
    }
    __syncthreads();

    for (int b = tid; b < B; b += blockDim.x) {
        int prev = b ? s_cu[b - 1] : 0;
        int nd   = s_cu[b] - prev;
        int n    = nd < L ? nd : L;
        float pi = 1.0f, U = 1.0f;
        int last = -1;
        for (int i = 0; i < n; i++) {
            int t = prev + i;
            pi = fminf(pi * s_r[t], 1.0f);
            U *= s_u[t];
            if (s_ok[t] && pi >= U) last = i;
        }
        int rejected = (nd > 0) && (last != nd - 1);
        int rr = prev + last + 1;
        rr = max(0, min(rr, NT - 1));
        int wc = rejected ? (last + 1) : n;
        g_meta[b] = make_int4(rejected, rr, wc, 0);
        for (int c = 0; c <= L; c++) {
            int val = (c < L && c <= last && (prev + c) < MAXNT) ? s_d[prev + c] : -1;
            if (c == wc) val = rejected ? -1 : __ldg(&bonus[b]);
            out[b * (L + 1) + c] = (float)val;
        }
    }
}

// ---------------------------------------------------------------------------
// Kernel B: sliced argmax via TMA bulk copy into smem.
// ---------------------------------------------------------------------------
__global__ void __launch_bounds__(TPB)
argmax_kernel(const float* __restrict__ target_probs,
              float* __restrict__ out, int V, int L)
{
    const int s   = blockIdx.x;
    const int b   = blockIdx.y;
    const int tid = threadIdx.x;

    __shared__ alignas(128) float4 buf[BUF_F4];
    __shared__ unsigned long long mbar;
    __shared__ float    s_wmax[TPB / 32];
    __shared__ float    s_bmax;
    __shared__ unsigned s_minidx;

    const int4 meta = g_meta[b];
    if (!meta.x) return;                 // not rejected: nothing to do

    const int nv4    = V >> 2;
    const int chunk4 = (nv4 + S - 1) / S;
    const int start4 = s * chunk4;
    const int end4   = min(nv4, start4 + chunk4);
    const int n4     = end4 - start4;

    const float4* __restrict__ src4 =
        (const float4*)target_probs + (long long)meta.y * nv4 + start4;
    const float* __restrict__ row = target_probs + (long long)meta.y * V;

    const bool bulk = (n4 > 0) && (n4 <= BUF_F4);

    unsigned mbar_a = (unsigned)__cvta_generic_to_shared(&mbar);
    unsigned buf_a  = (unsigned)__cvta_generic_to_shared(buf);

    if (tid == 0) {
        s_minidx = 0xFFFFFFFFu;
        if (bulk)
            asm volatile("mbarrier.init.shared.b64 [%0], %1;"
                         :: "r"(mbar_a), "r"(1) : "memory");
    }
    __syncthreads();

    if (bulk) {
        if (tid == 0) {
            unsigned bytes = (unsigned)n4 * 16u;
            asm volatile("mbarrier.arrive.expect_tx.shared.b64 _, [%0], %1;"
                         :: "r"(mbar_a), "r"(bytes) : "memory");
            asm volatile(
                "cp.async.bulk.shared::cta.global.mbarrier::complete_tx::bytes "
                "[%0], [%1], %2, [%3];"
                :: "r"(buf_a), "l"(src4), "r"(bytes), "r"(mbar_a) : "memory");
        }
        // wait (acquire) on parity 0 — barrier is fresh each launch/replay
        unsigned done = 0;
        while (!done) {
            asm volatile(
                "{\n\t.reg .pred p;\n\t"
                "mbarrier.try_wait.parity.acquire.cta.shared::cta.b64 p, [%1], %2, 0x989680;\n\t"
                "selp.b32 %0, 1, 0, p;\n\t}"
                : "=r"(done) : "r"(mbar_a), "r"(0) : "memory");
        }
    }

    const float4* base = bulk ? (const float4*)buf : src4;

    // ---- Pass 1: pure value max (smem-resident if bulk) ----
    float m0 = -1.0f, m1 = -1.0f, m2 = -1.0f, m3 = -1.0f;
    #pragma unroll 4
    for (int j = tid; j < n4; j += TPB) {
        float4 v = base[j];
        m0 = fmaxf(m0, v.x);
        m1 = fmaxf(m1, v.y);
        m2 = fmaxf(m2, v.z);
        m3 = fmaxf(m3, v.w);
    }
    float m = fmaxf(fmaxf(m0, m1), fmaxf(m2, m3));
    if ((V & 3) && s == S - 1) {          // scalar tail straight from gmem
        for (int i = (nv4 << 2) + tid; i < V; i += TPB)
            m = fmaxf(m, row[i]);
    }
    #pragma unroll
    for (int off = 16; off > 0; off >>= 1)
        m = fmaxf(m, __shfl_down_sync(0xFFFFFFFFu, m, off));
    if ((tid & 31) == 0) s_wmax[tid >> 5] = m;
    __syncthreads();
    if (tid < 32) {
        float v = (tid < (TPB / 32)) ? s_wmax[tid] : -1.0f;
        #pragma unroll
        for (int off = 16; off > 0; off >>= 1)
            v = fmaxf(v, __shfl_down_sync(0xFFFFFFFFu, v, off));
        if (tid == 0) s_bmax = v;
    }
    __syncthreads();

    // ---- Pass 2: first index bit-equal to max (smem-resident if bulk) ----
    const unsigned mbits = __float_as_uint(s_bmax);   // probs >= 0
    unsigned lmin = 0xFFFFFFFFu;
    #pragma unroll 4
    for (int j = tid; j < n4; j += TPB) {
        float4 v = base[j];
        unsigned gi = (unsigned)((start4 + j) << 2);
        if (__float_as_uint(v.x) == mbits) lmin = min(lmin, gi);
        if (__float_as_uint(v.y) == mbits) lmin = min(lmin, gi + 1);
        if (__float_as_uint(v.z) == mbits) lmin = min(lmin, gi + 2);
        if (__float_as_uint(v.w) == mbits) lmin = min(lmin, gi + 3);
    }
    if ((V & 3) && s == S - 1) {
        for (int i = (nv4 << 2) + tid; i < V; i += TPB)
            if (__float_as_uint(row[i]) == mbits) lmin = min(lmin, (unsigned)i);
    }
    if (lmin != 0xFFFFFFFFu) atomicMin(&s_minidx, lmin);
    __syncthreads();

    // ---- publish; last block for this request finalizes ----
    if (tid == 0) {
        unsigned long long key = (n4 > 0 || ((V & 3) && s == S - 1))
            ? (((unsigned long long)mbits << 32) | (0xFFFFFFFFu - s_minidx))
            : 0ull;
        g_slot[b * S + s] = key;
        __threadfence();
        int old = atomicAdd(&g_count[b], 1);
        if (old == S - 1) {
            unsigned long long best = 0ull;
            #pragma unroll
            for (int j = 0; j < S; j++) {
                unsigned long long w = g_slot[b * S + j];
                if (w > best) best = w;
            }
            int rec = (int)(0xFFFFFFFFu - (unsigned)(best & 0xFFFFFFFFull));
            out[b * (L + 1) + meta.z] = (float)rec;
            g_count[b] = 0;   // self-reset for next replay
        }
    }
}

extern "C" void kernel_launch(void* const* d_in, const int* in_sizes, int n_in,
                              void* d_out, int out_size) {
    const float* draft_probs     = (const float*)d_in[0];
    const float* target_probs    = (const float*)d_in[1];
    const float* uniform_probs   = (const float*)d_in[2];
    const int*   draft_token_ids = (const int*)  d_in[3];
    const int*   cu              = (const int*)  d_in[4];
    const int*   bonus           = (const int*)  d_in[5];
    float*       out             = (float*)d_out;

    const int NT = in_sizes[2];
    const int V  = in_sizes[0] / NT;
    const int B  = in_sizes[4];
    const int L  = out_size / B - 1;

    scan_kernel<<<1, 512>>>(draft_probs, target_probs, uniform_probs,
                            draft_token_ids, cu, bonus, out, V, NT, B, L);
    argmax_kernel<<<dim3(S, B), TPB>>>(target_probs, out, V, L);
}